// round 2
// baseline (speedup 1.0000x reference)
#include <cuda_runtime.h>
#include <cstddef>

#define B 32
#define L 128
#define D 256
#define T 10000
#define TN 128   // t-tile per block in item kernel

// ---------------- device scratch (no allocations allowed) ----------------
__device__ float g_dm[B * D];
__device__ float g_q[4 * B * T];
__device__ float g_item[B * T];
__device__ float g_norm[5 * B];   // [w*B+b], w=0..3 -> q norms, w=4 -> item norm

__device__ __forceinline__ float fast_tanh(float x) {
    float y;
    asm("tanh.approx.f32 %0, %1;" : "=f"(y) : "f"(x));
    return y;
}

__device__ __forceinline__ void ld8(const float* __restrict__ p, float* r) {
    float4 v0 = __ldg((const float4*)p);
    float4 v1 = __ldg((const float4*)(p + 4));
    r[0] = v0.x; r[1] = v0.y; r[2] = v0.z; r[3] = v0.w;
    r[4] = v1.x; r[5] = v1.y; r[6] = v1.z; r[7] = v1.w;
}

// ---------------- dm[b,d] = mean_l data[b,l,d] ----------------
__global__ void dm_kernel(const float* __restrict__ data) {
    const int b = blockIdx.x;
    const int d = threadIdx.x;          // 256 threads
    const float* p = data + (size_t)b * L * D + d;
    float s = 0.f;
#pragma unroll 8
    for (int l = 0; l < L; ++l) s += p[(size_t)l * D];
    g_dm[b * D + d] = s * (1.0f / (float)L);
}

// ---------------- q[w][b,t] = dm[b,:] . W_w[t,:] ----------------
// block: 256 threads = 8 warps; warp handles 16 consecutive t; lane = b.
__global__ void q_kernel(const float* __restrict__ W1, const float* __restrict__ W2,
                         const float* __restrict__ W3, const float* __restrict__ W4) {
    __shared__ float dmt[D][B];   // transposed dm, 32 KB
    const int tid = threadIdx.x;
    for (int i = tid; i < B * D; i += 256) {
        int b = i >> 8;
        int d = i & 255;
        dmt[d][b] = g_dm[i];
    }
    __syncthreads();

    const float* W = (blockIdx.y == 0) ? W1 : (blockIdx.y == 1) ? W2
                   : (blockIdx.y == 2) ? W3 : W4;
    float* q = g_q + (size_t)blockIdx.y * B * T;

    const int warp = tid >> 5;
    const int lane = tid & 31;     // lane == b
    const int t0 = blockIdx.x * 128 + warp * 16;

    for (int it = 0; it < 16; ++it) {
        const int t = t0 + it;
        if (t >= T) break;
        const float4* wr = (const float4*)(W + (size_t)t * D);
        float s = 0.f;
#pragma unroll
        for (int k4 = 0; k4 < D / 4; ++k4) {
            float4 w4 = __ldg(&wr[k4]);          // warp-uniform load
            const int d = k4 * 4;
            s += w4.x * dmt[d + 0][lane];
            s += w4.y * dmt[d + 1][lane];
            s += w4.z * dmt[d + 2][lane];
            s += w4.w * dmt[d + 3][lane];
        }
        q[(size_t)lane * T + t] = s;
    }
}

// ---------------- main fused kernel ----------------
// item_raw[b,t] = sum_l tanh(emb[ev[b,l]] . W5[t]) * drop[b,l,t] * corr[ev[b,l]-1, t]
// One block per (t-tile, b). M=L=128, N=TN=128, K=256 (16-wide chunks).
__global__ __launch_bounds__(256, 2)
void item_kernel(const int* __restrict__ event_type,
                 const float* __restrict__ emb,
                 const float* __restrict__ corr,
                 const float* __restrict__ W5,
                 const float* __restrict__ drop) {
    __shared__ float As[16][136];
    __shared__ float Bs[16][136];
    __shared__ int   sEid[L];
    __shared__ float sRed[16][TN];

    const int b = blockIdx.y;
    const int tBase = blockIdx.x * TN;
    const int tid = threadIdx.x;
    const int tx = tid & 15;
    const int ty = tid >> 4;
    const int la = tid >> 1;            // row (l for A, t-local for B) this thread loads
    const int ha = (tid & 1) << 3;      // k sub-offset {0,8}

    if (tid < L) sEid[tid] = event_type[b * L + tid];
    __syncthreads();

    const float* aRow = emb + (size_t)sEid[la] * D + ha;
    const int tb = tBase + la;
    const bool bOk = (tb < T);
    const float* bRow = W5 + (size_t)(bOk ? tb : 0) * D + ha;

    float acc[8][8];
#pragma unroll
    for (int i = 0; i < 8; ++i)
#pragma unroll
        for (int j = 0; j < 8; ++j) acc[i][j] = 0.f;

    float ra[8], rb[8];
    ld8(aRow, ra);
    ld8(bRow, rb);
    if (!bOk) {
#pragma unroll
        for (int j = 0; j < 8; ++j) rb[j] = 0.f;
    }

#pragma unroll 1
    for (int c = 0; c < 16; ++c) {
#pragma unroll
        for (int j = 0; j < 8; ++j) {
            As[ha + j][la] = ra[j];
            Bs[ha + j][la] = rb[j];
        }
        __syncthreads();
        if (c < 15) {
            ld8(aRow + (c + 1) * 16, ra);
            ld8(bRow + (c + 1) * 16, rb);
            if (!bOk) {
#pragma unroll
                for (int j = 0; j < 8; ++j) rb[j] = 0.f;
            }
        }
#pragma unroll
        for (int kk = 0; kk < 16; ++kk) {
            float af[8], bf[8];
            *(float4*)&af[0] = *(const float4*)&As[kk][ty * 8];
            *(float4*)&af[4] = *(const float4*)&As[kk][ty * 8 + 4];
            *(float4*)&bf[0] = *(const float4*)&Bs[kk][tx * 8];
            *(float4*)&bf[4] = *(const float4*)&Bs[kk][tx * 8 + 4];
#pragma unroll
            for (int i = 0; i < 8; ++i)
#pragma unroll
                for (int j = 0; j < 8; ++j)
                    acc[i][j] += af[i] * bf[j];
        }
        __syncthreads();
    }

    // ---- fused epilogue: tanh * drop * corr, partial reduce over this thread's 8 l's ----
    const int tg0 = tBase + tx * 8;
    float partial[8];
#pragma unroll
    for (int j = 0; j < 8; ++j) partial[j] = 0.f;

#pragma unroll 1
    for (int i = 0; i < 8; ++i) {
        const int l = ty * 8 + i;
        const int e = sEid[l];
        if (e == 0) continue;                      // padding id -> zero contribution
        const int idx = e - 1;
        const float* dr = drop + ((size_t)(b * L + l)) * T + tg0;
        const float* cr = corr + (size_t)idx * T + tg0;
        if (tg0 + 8 <= T) {
            float d0[8], c0[8];
            ld8(dr, d0);
            ld8(cr, c0);
#pragma unroll
            for (int j = 0; j < 8; ++j)
                partial[j] += fast_tanh(acc[i][j]) * d0[j] * c0[j];
        } else {
#pragma unroll
            for (int j = 0; j < 8; ++j)
                if (tg0 + j < T)
                    partial[j] += fast_tanh(acc[i][j]) * __ldg(dr + j) * __ldg(cr + j);
        }
    }

#pragma unroll
    for (int j = 0; j < 8; ++j) sRed[ty][tx * 8 + j] = partial[j];
    __syncthreads();

    if (tid < TN) {
        float s = 0.f;
#pragma unroll
        for (int r = 0; r < 16; ++r) s += sRed[r][tid];
        const int t = tBase + tid;
        if (t < T) g_item[(size_t)b * T + t] = s;
    }
}

// ---------------- norms: ||q_w[b]||, ||item[b]|| ----------------
__global__ void norm_kernel() {
    const int b = blockIdx.x;
    const int tid = threadIdx.x;
    float s0 = 0, s1 = 0, s2 = 0, s3 = 0, s4 = 0;
    for (int t = tid; t < T; t += 256) {
        float v;
        v = g_q[0 * B * T + (size_t)b * T + t]; s0 += v * v;
        v = g_q[1 * B * T + (size_t)b * T + t]; s1 += v * v;
        v = g_q[2 * B * T + (size_t)b * T + t]; s2 += v * v;
        v = g_q[3 * B * T + (size_t)b * T + t]; s3 += v * v;
        v = g_item[(size_t)b * T + t];          s4 += v * v;
    }
    __shared__ float sm[5][256];
    sm[0][tid] = s0; sm[1][tid] = s1; sm[2][tid] = s2; sm[3][tid] = s3; sm[4][tid] = s4;
    __syncthreads();
    for (int off = 128; off > 0; off >>= 1) {
        if (tid < off) {
#pragma unroll
            for (int w = 0; w < 5; ++w) sm[w][tid] += sm[w][tid + off];
        }
        __syncthreads();
    }
    if (tid < 5) g_norm[tid * B + b] = fmaxf(sqrtf(sm[tid][0]), 1e-5f);
}

// ---------------- final combine ----------------
__global__ void final_kernel(const float* __restrict__ pa, const float* __restrict__ pb,
                             const float* __restrict__ pc, const float* __restrict__ pd,
                             float* __restrict__ out) {
    const int b = blockIdx.y;
    const int t = blockIdx.x * 256 + threadIdx.x;
    if (t >= T) return;
    const float i0 = 1.f / g_norm[0 * B + b];
    const float i1 = 1.f / g_norm[1 * B + b];
    const float i2 = 1.f / g_norm[2 * B + b];
    const float i3 = 1.f / g_norm[3 * B + b];
    const float i4 = 1.f / g_norm[4 * B + b];
    const float ca = pa[0], cb = pb[0], cc = pc[0], cd = pd[0];
    float s = g_q[0 * B * T + (size_t)b * T + t] * i0 * ca
            + g_q[1 * B * T + (size_t)b * T + t] * i1 * cb
            + g_q[2 * B * T + (size_t)b * T + t] * i2 * cc
            + g_q[3 * B * T + (size_t)b * T + t] * i3 * cd
            + g_item[(size_t)b * T + t] * i4;
    out[(size_t)b * T + t] = tanhf(s);
}

// ---------------- target ----------------
__global__ void target_fill(float* __restrict__ tgt) {
    const int i = blockIdx.x * 256 + threadIdx.x;
    if (i < B * T) tgt[i] = 1.f;
}

__global__ void target_scatter(const int* __restrict__ event_type, float* __restrict__ tgt) {
    const int i = blockIdx.x * 256 + threadIdx.x;
    if (i < B * L) {
        const int e = event_type[i];
        if (e != 0) tgt[(size_t)(i >> 7) * T + (e - 1)] = 0.f;
    }
}

// ---------------- launch ----------------
extern "C" void kernel_launch(void* const* d_in, const int* in_sizes, int n_in,
                              void* d_out, int out_size) {
    const float* data = (const float*)d_in[0];
    const int*   ev   = (const int*)d_in[1];
    const float* emb  = (const float*)d_in[2];
    const float* corr = (const float*)d_in[3];
    const float* W1   = (const float*)d_in[4];
    const float* W2   = (const float*)d_in[5];
    const float* W3   = (const float*)d_in[6];
    const float* W4   = (const float*)d_in[7];
    const float* W5   = (const float*)d_in[8];
    const float* a    = (const float*)d_in[9];
    const float* bb   = (const float*)d_in[10];
    const float* c    = (const float*)d_in[11];
    const float* dd   = (const float*)d_in[12];
    const float* drop = (const float*)d_in[13];

    float* out = (float*)d_out;
    float* tgt = out + B * T;

    dm_kernel<<<B, 256>>>(data);
    q_kernel<<<dim3((T + 127) / 128, 4), 256>>>(W1, W2, W3, W4);
    item_kernel<<<dim3((T + TN - 1) / TN, B), 256>>>(ev, emb, corr, W5, drop);
    norm_kernel<<<B, 256>>>();
    final_kernel<<<dim3((T + 255) / 256, B), 256>>>(a, bb, c, dd, out);
    target_fill<<<(B * T + 255) / 256, 256>>>(tgt);
    target_scatter<<<(B * L + 255) / 256, 256>>>(ev, tgt);
}

// round 4
// speedup vs baseline: 1.5990x; 1.5990x over previous
#include <cuda_runtime.h>
#include <cuda_bf16.h>
#include <cstdint>
#include <cstddef>

#define B 32
#define L 128
#define D 256
#define T 10000
#define TN 128
#define NTILES 79      // ceil(10000/128)
#define NSPLIT 10
#define SA 40          // smem row stride in bf16 (80B: 16B-aligned, conflict-free ldmatrix)
#define KC 32          // K chunk

// ---------------- device scratch (no runtime allocations) ----------------
__device__ float g_dm[B * D];
__device__ float g_q[4 * B * T];
__device__ float g_item[B * T];
__device__ float g_norm2[5 * B];
__device__ __nv_bfloat16 g_w5_hi[T * D];
__device__ __nv_bfloat16 g_w5_lo[T * D];
__device__ __nv_bfloat16 g_emb_hi[(T + 1) * D];
__device__ __nv_bfloat16 g_emb_lo[(T + 1) * D];

// ---------------- helpers ----------------
__device__ __forceinline__ float fast_tanh(float x) {
    float y;
    asm("tanh.approx.f32 %0, %1;" : "=f"(y) : "f"(x));
    return y;
}

__device__ __forceinline__ uint32_t smem_u32(const void* p) {
    uint32_t a;
    asm("{ .reg .u64 t; cvta.to.shared.u64 t, %1; cvt.u32.u64 %0, t; }" : "=r"(a) : "l"(p));
    return a;
}

__device__ __forceinline__ void ldm_x4(uint32_t* f, uint32_t addr) {
    asm volatile("ldmatrix.sync.aligned.m8n8.x4.shared.b16 {%0,%1,%2,%3}, [%4];"
                 : "=r"(f[0]), "=r"(f[1]), "=r"(f[2]), "=r"(f[3]) : "r"(addr));
}

__device__ __forceinline__ void mma16816(float* c, const uint32_t* a, const uint32_t* b) {
    asm volatile(
        "mma.sync.aligned.m16n8k16.row.col.f32.bf16.bf16.f32 "
        "{%0,%1,%2,%3},{%4,%5,%6,%7},{%8,%9},{%0,%1,%2,%3};"
        : "+f"(c[0]), "+f"(c[1]), "+f"(c[2]), "+f"(c[3])
        : "r"(a[0]), "r"(a[1]), "r"(a[2]), "r"(a[3]), "r"(b[0]), "r"(b[1]));
}

// ---------------- precompute: bf16 hi/lo split tables ----------------
__global__ void cvt_kernel(const float* __restrict__ w5, const float* __restrict__ emb) {
    const int i = blockIdx.x * 256 + threadIdx.x;
    if (i < T * D) {
        float x = w5[i];
        __nv_bfloat16 h = __float2bfloat16(x);
        g_w5_hi[i] = h;
        g_w5_lo[i] = __float2bfloat16(x - __bfloat162float(h));
    }
    if (i < (T + 1) * D) {
        float x = emb[i];
        __nv_bfloat16 h = __float2bfloat16(x);
        g_emb_hi[i] = h;
        g_emb_lo[i] = __float2bfloat16(x - __bfloat162float(h));
    }
}

// ---------------- dm[b,d] = mean_l data[b,l,d]  (+ zero g_norm2) ----------------
__global__ void dm_kernel(const float* __restrict__ data) {
    const int b = blockIdx.x;
    const int d = threadIdx.x;
    if (b == 0 && d < 5 * B) g_norm2[d] = 0.f;
    const float* p = data + (size_t)b * L * D + d;
    float s = 0.f;
#pragma unroll 8
    for (int l = 0; l < L; ++l) s += p[(size_t)l * D];
    g_dm[b * D + d] = s * (1.0f / (float)L);
}

// ---------------- q[w][b,t] = dm[b,:] . W_w[t,:] ----------------
__global__ void q_kernel(const float* __restrict__ W1, const float* __restrict__ W2,
                         const float* __restrict__ W3, const float* __restrict__ W4) {
    __shared__ float dmt[D][B];
    const int tid = threadIdx.x;
    for (int i = tid; i < B * D; i += 256) {
        int b = i >> 8;
        int d = i & 255;
        dmt[d][b] = g_dm[i];
    }
    __syncthreads();

    const float* W = (blockIdx.y == 0) ? W1 : (blockIdx.y == 1) ? W2
                   : (blockIdx.y == 2) ? W3 : W4;
    float* q = g_q + (size_t)blockIdx.y * B * T;

    const int warp = tid >> 5;
    const int lane = tid & 31;
    const int t0 = blockIdx.x * 128 + warp * 16;

    for (int it = 0; it < 16; ++it) {
        const int t = t0 + it;
        if (t >= T) break;
        const float4* wr = (const float4*)(W + (size_t)t * D);
        float s = 0.f;
#pragma unroll
        for (int k4 = 0; k4 < D / 4; ++k4) {
            float4 w4 = __ldg(&wr[k4]);
            const int d = k4 * 4;
            s += w4.x * dmt[d + 0][lane];
            s += w4.y * dmt[d + 1][lane];
            s += w4.z * dmt[d + 2][lane];
            s += w4.w * dmt[d + 3][lane];
        }
        q[(size_t)lane * T + t] = s;
    }
}

// ---------------- main fused tensor-core (HMMA) kernel ----------------
// item_raw[b,t] = sum_l tanh(emb[ev[b,l]].W5[t]) * drop[b,l,t] * corr[ev[b,l]-1,t]
// CTA = (t-tile 128, batch b). M=L=128, N=128, K=256 (chunks of 32).
// bf16 hi/lo split: full = hi*hi + hi*lo + lo*hi.
__global__ __launch_bounds__(256, 1)
void item_kernel(const int* __restrict__ event_type,
                 const float* __restrict__ corr,
                 const float* __restrict__ drop) {
    __shared__ __nv_bfloat16 sAh[128 * SA];
    __shared__ __nv_bfloat16 sAl[128 * SA];
    __shared__ __nv_bfloat16 sBh[128 * SA];
    __shared__ __nv_bfloat16 sBl[128 * SA];
    __shared__ int   sEid[L];
    __shared__ float red[4][128];

    const int tid  = threadIdx.x;
    const int warp = tid >> 5;
    const int lane = tid & 31;
    const int wm   = warp & 3;        // M block (32 rows)
    const int wn   = warp >> 2;       // N block (64 cols)
    const int b     = blockIdx.y;
    const int tBase = blockIdx.x * TN;

    if (tid < L) sEid[tid] = event_type[b * L + tid];
    __syncthreads();

    // --- global load setup: 2 threads per row, each 2 uint4 (16 bf16) per array ---
    const int row  = tid >> 1;
    const int half = tid & 1;          // which 16-bf16 half of the 32-wide chunk
    const int eid  = sEid[row];
    const int trow = tBase + row;
    const bool tOk = trow < T;

    const uint4* gAh = (const uint4*)(g_emb_hi + (size_t)eid * D) + half * 2;
    const uint4* gAl = (const uint4*)(g_emb_lo + (size_t)eid * D) + half * 2;
    const uint4* gBh = (const uint4*)(g_w5_hi + (size_t)(tOk ? trow : 0) * D) + half * 2;
    const uint4* gBl = (const uint4*)(g_w5_lo + (size_t)(tOk ? trow : 0) * D) + half * 2;
    const uint4 z4 = make_uint4(0, 0, 0, 0);

    uint4 pf[8];
    // prefetch chunk 0 (chunk stride in uint4 units: KC bf16 = 4 uint4)
    pf[0] = __ldg(gAh + 0); pf[1] = __ldg(gAh + 1);
    pf[2] = __ldg(gAl + 0); pf[3] = __ldg(gAl + 1);
    pf[4] = tOk ? __ldg(gBh + 0) : z4; pf[5] = tOk ? __ldg(gBh + 1) : z4;
    pf[6] = tOk ? __ldg(gBl + 0) : z4; pf[7] = tOk ? __ldg(gBl + 1) : z4;

    float acc[2][8][4];
#pragma unroll
    for (int i = 0; i < 2; ++i)
#pragma unroll
        for (int j = 0; j < 8; ++j)
#pragma unroll
            for (int r = 0; r < 4; ++r) acc[i][j][r] = 0.f;

    // smem store target for this thread (bf16 index)
    const int stoff = row * SA + half * 16;

    // ldmatrix base addresses (byte offsets computed per k-step)
    const uint32_t aAh = smem_u32(sAh), aAl = smem_u32(sAl);
    const uint32_t aBh = smem_u32(sBh), aBl = smem_u32(sBl);

    // A frag address: row = wm*32 + i*16 + ((lane>>3)&1)*8 + (lane&7), col = kk*16 + (lane>>4)*8
    const int arow_base = wm * 32 + ((lane >> 3) & 1) * 8 + (lane & 7);
    const int acol_sub  = (lane >> 4) * 8;
    // B frag address: row = wn*64 + jp*16 + ((lane>>4)&1)*8 + (lane&7), col = kk*16 + ((lane>>3)&1)*8
    const int brow_base = wn * 64 + ((lane >> 4) & 1) * 8 + (lane & 7);
    const int bcol_sub  = ((lane >> 3) & 1) * 8;

#pragma unroll 1
    for (int c = 0; c < 8; ++c) {
        // store prefetched chunk
        *(uint4*)(sAh + stoff)     = pf[0];
        *(uint4*)(sAh + stoff + 8) = pf[1];
        *(uint4*)(sAl + stoff)     = pf[2];
        *(uint4*)(sAl + stoff + 8) = pf[3];
        *(uint4*)(sBh + stoff)     = pf[4];
        *(uint4*)(sBh + stoff + 8) = pf[5];
        *(uint4*)(sBl + stoff)     = pf[6];
        *(uint4*)(sBl + stoff + 8) = pf[7];
        __syncthreads();

        if (c < 7) {
            const int o = (c + 1) * 4;   // uint4 offset of next chunk
            pf[0] = __ldg(gAh + o); pf[1] = __ldg(gAh + o + 1);
            pf[2] = __ldg(gAl + o); pf[3] = __ldg(gAl + o + 1);
            pf[4] = tOk ? __ldg(gBh + o) : z4; pf[5] = tOk ? __ldg(gBh + o + 1) : z4;
            pf[6] = tOk ? __ldg(gBl + o) : z4; pf[7] = tOk ? __ldg(gBl + o + 1) : z4;
        }

#pragma unroll
        for (int kk = 0; kk < 2; ++kk) {
            uint32_t a_h[2][4], a_l[2][4], b_h[8][2], b_l[8][2];
#pragma unroll
            for (int i = 0; i < 2; ++i) {
                const uint32_t off = (uint32_t)((arow_base + i * 16) * SA + kk * 16 + acol_sub) * 2;
                ldm_x4(a_h[i], aAh + off);
                ldm_x4(a_l[i], aAl + off);
            }
#pragma unroll
            for (int jp = 0; jp < 4; ++jp) {
                const uint32_t off = (uint32_t)((brow_base + jp * 16) * SA + kk * 16 + bcol_sub) * 2;
                ldm_x4(&b_h[jp * 2][0], aBh + off);   // fills b_h[2jp][0..1], b_h[2jp+1][0..1]
                ldm_x4(&b_l[jp * 2][0], aBl + off);
            }
#pragma unroll
            for (int i = 0; i < 2; ++i)
#pragma unroll
                for (int j = 0; j < 8; ++j) {
                    mma16816(acc[i][j], a_h[i], b_h[j]);
                    mma16816(acc[i][j], a_h[i], b_l[j]);
                    mma16816(acc[i][j], a_l[i], b_h[j]);
                }
        }
        __syncthreads();
    }

    // ---- fused epilogue: tanh * drop * corr, reduce over rows (l) ----
    float pcol[16];
#pragma unroll
    for (int k = 0; k < 16; ++k) pcol[k] = 0.f;

#pragma unroll
    for (int i = 0; i < 2; ++i) {
#pragma unroll
        for (int p = 0; p < 2; ++p) {
            const int r = wm * 32 + i * 16 + (lane >> 2) + p * 8;   // l index
            const int e = sEid[r];
            const float* dr = drop + ((size_t)(b * L + r)) * T;
            const float* cr = corr + (size_t)(e - 1) * T;
#pragma unroll
            for (int j = 0; j < 8; ++j) {
                const int col = tBase + wn * 64 + j * 8 + (lane & 3) * 2;
                if (e > 0 && col < T) {   // col even, T even: pair never straddles
                    const float2 d2 = __ldg((const float2*)(dr + col));
                    const float2 c2 = __ldg((const float2*)(cr + col));
                    pcol[j * 2 + 0] += fast_tanh(acc[i][j][p * 2 + 0]) * d2.x * c2.x;
                    pcol[j * 2 + 1] += fast_tanh(acc[i][j][p * 2 + 1]) * d2.y * c2.y;
                }
            }
        }
    }

    // reduce over the 8 row-groups within the warp (lanes sharing lane&3)
#pragma unroll
    for (int mask = 4; mask <= 16; mask <<= 1)
#pragma unroll
        for (int k = 0; k < 16; ++k)
            pcol[k] += __shfl_xor_sync(0xffffffffu, pcol[k], mask);

    if (lane < 4) {
#pragma unroll
        for (int j = 0; j < 8; ++j) {
            red[wm][wn * 64 + j * 8 + lane * 2 + 0] = pcol[j * 2 + 0];
            red[wm][wn * 64 + j * 8 + lane * 2 + 1] = pcol[j * 2 + 1];
        }
    }
    __syncthreads();

    if (tid < 128) {
        const int t = tBase + tid;
        if (t < T) {
            const float s = red[0][tid] + red[1][tid] + red[2][tid] + red[3][tid];
            g_item[(size_t)b * T + t] = s;
        }
    }
}

// ---------------- norms: sum of squares via split + atomics ----------------
__global__ void norm_kernel() {
    const int b = blockIdx.x, s = blockIdx.y, tid = threadIdx.x;
    const int t0 = s * (T / NSPLIT), t1 = t0 + (T / NSPLIT);
    float a0 = 0, a1 = 0, a2 = 0, a3 = 0, a4 = 0;
    for (int t = t0 + tid; t < t1; t += 256) {
        float v;
        v = g_q[0 * B * T + (size_t)b * T + t]; a0 += v * v;
        v = g_q[1 * B * T + (size_t)b * T + t]; a1 += v * v;
        v = g_q[2 * B * T + (size_t)b * T + t]; a2 += v * v;
        v = g_q[3 * B * T + (size_t)b * T + t]; a3 += v * v;
        v = g_item[(size_t)b * T + t];          a4 += v * v;
    }
#pragma unroll
    for (int o = 16; o; o >>= 1) {
        a0 += __shfl_xor_sync(0xffffffffu, a0, o);
        a1 += __shfl_xor_sync(0xffffffffu, a1, o);
        a2 += __shfl_xor_sync(0xffffffffu, a2, o);
        a3 += __shfl_xor_sync(0xffffffffu, a3, o);
        a4 += __shfl_xor_sync(0xffffffffu, a4, o);
    }
    __shared__ float sm[5][8];
    if ((tid & 31) == 0) {
        const int w = tid >> 5;
        sm[0][w] = a0; sm[1][w] = a1; sm[2][w] = a2; sm[3][w] = a3; sm[4][w] = a4;
    }
    __syncthreads();
    if (tid < 5) {
        float t5 = 0;
#pragma unroll
        for (int k = 0; k < 8; ++k) t5 += sm[tid][k];
        atomicAdd(&g_norm2[tid * B + b], t5);
    }
}

// ---------------- final combine ----------------
__global__ void final_kernel(const float* __restrict__ pa, const float* __restrict__ pb,
                             const float* __restrict__ pc, const float* __restrict__ pd,
                             float* __restrict__ out) {
    const int b = blockIdx.y;
    const int t = blockIdx.x * 256 + threadIdx.x;
    if (t >= T) return;
    auto inv = [](float n2) { return (n2 > 1e-10f) ? rsqrtf(n2) : 1e5f; };
    const float i0 = inv(g_norm2[0 * B + b]);
    const float i1 = inv(g_norm2[1 * B + b]);
    const float i2 = inv(g_norm2[2 * B + b]);
    const float i3 = inv(g_norm2[3 * B + b]);
    const float i4 = inv(g_norm2[4 * B + b]);
    const float ca = pa[0], cb = pb[0], cc = pc[0], cd = pd[0];
    float s = g_q[0 * B * T + (size_t)b * T + t] * i0 * ca
            + g_q[1 * B * T + (size_t)b * T + t] * i1 * cb
            + g_q[2 * B * T + (size_t)b * T + t] * i2 * cc
            + g_q[3 * B * T + (size_t)b * T + t] * i3 * cd
            + g_item[(size_t)b * T + t] * i4;
    out[(size_t)b * T + t] = tanhf(s);
}

// ---------------- target ----------------
__global__ void target_fill(float* __restrict__ tgt) {
    const int i = blockIdx.x * 256 + threadIdx.x;
    if (i < B * T) tgt[i] = 1.f;
}

__global__ void target_scatter(const int* __restrict__ event_type, float* __restrict__ tgt) {
    const int i = blockIdx.x * 256 + threadIdx.x;
    if (i < B * L) {
        const int e = event_type[i];
        if (e != 0) tgt[(size_t)(i >> 7) * T + (e - 1)] = 0.f;
    }
}

// ---------------- launch ----------------
extern "C" void kernel_launch(void* const* d_in, const int* in_sizes, int n_in,
                              void* d_out, int out_size) {
    const float* data = (const float*)d_in[0];
    const int*   ev   = (const int*)d_in[1];
    const float* emb  = (const float*)d_in[2];
    const float* corr = (const float*)d_in[3];
    const float* W1   = (const float*)d_in[4];
    const float* W2   = (const float*)d_in[5];
    const float* W3   = (const float*)d_in[6];
    const float* W4   = (const float*)d_in[7];
    const float* W5   = (const float*)d_in[8];
    const float* a    = (const float*)d_in[9];
    const float* bb   = (const float*)d_in[10];
    const float* c    = (const float*)d_in[11];
    const float* dd   = (const float*)d_in[12];
    const float* drop = (const float*)d_in[13];

    float* out = (float*)d_out;
    float* tgt = out + B * T;

    cvt_kernel<<<((T + 1) * D + 255) / 256, 256>>>(W5, emb);
    dm_kernel<<<B, 256>>>(data);
    q_kernel<<<dim3((T + 127) / 128, 4), 256>>>(W1, W2, W3, W4);
    item_kernel<<<dim3(NTILES, B), 256>>>(ev, corr, drop);
    norm_kernel<<<dim3(B, NSPLIT), 256>>>();
    final_kernel<<<dim3((T + 255) / 256, B), 256>>>(a, bb, c, dd, out);
    target_fill<<<(B * T + 255) / 256, 256>>>(tgt);
    target_scatter<<<(B * L + 255) / 256, 256>>>(ev, tgt);
}

// round 5
// speedup vs baseline: 2.0704x; 1.2948x over previous
#include <cuda_runtime.h>
#include <cuda_bf16.h>
#include <cstdint>
#include <cstddef>

#define B 32
#define L 128
#define D 256
#define T 10000
#define TN 64          // t-tile per CTA
#define NTILES 157     // ceil(10000/64)
#define NSPLIT 10
#define SA 40          // smem row stride in bf16 (80B, conflict-free ldmatrix)

// ---------------- device scratch ----------------
__device__ float g_dm[B * D];
__device__ float g_q[4 * B * T];
__device__ float g_item[B * T];
__device__ float g_norm2[5 * B];
__device__ __nv_bfloat16 g_w5_hi[T * D];
__device__ __nv_bfloat16 g_w5_lo[T * D];
__device__ __nv_bfloat16 g_emb_hi[(T + 1) * D];
__device__ __nv_bfloat16 g_emb_lo[(T + 1) * D];

// ---------------- helpers ----------------
__device__ __forceinline__ float fast_tanh(float x) {
    float y;
    asm("tanh.approx.f32 %0, %1;" : "=f"(y) : "f"(x));
    return y;
}

__device__ __forceinline__ uint32_t smem_u32(const void* p) {
    uint32_t a;
    asm("{ .reg .u64 t; cvta.to.shared.u64 t, %1; cvt.u32.u64 %0, t; }" : "=r"(a) : "l"(p));
    return a;
}

__device__ __forceinline__ void ldm_x4(uint32_t* f, uint32_t addr) {
    asm volatile("ldmatrix.sync.aligned.m8n8.x4.shared.b16 {%0,%1,%2,%3}, [%4];"
                 : "=r"(f[0]), "=r"(f[1]), "=r"(f[2]), "=r"(f[3]) : "r"(addr));
}

__device__ __forceinline__ void mma16816(float* c, const uint32_t* a, const uint32_t* b) {
    asm volatile(
        "mma.sync.aligned.m16n8k16.row.col.f32.bf16.bf16.f32 "
        "{%0,%1,%2,%3},{%4,%5,%6,%7},{%8,%9},{%0,%1,%2,%3};"
        : "+f"(c[0]), "+f"(c[1]), "+f"(c[2]), "+f"(c[3])
        : "r"(a[0]), "r"(a[1]), "r"(a[2]), "r"(a[3]), "r"(b[0]), "r"(b[1]));
}

__device__ __forceinline__ void cp16(uint32_t dst, const void* src) {
    asm volatile("cp.async.cg.shared.global [%0], [%1], 16;" :: "r"(dst), "l"(src));
}

__device__ __forceinline__ void cp16z(uint32_t dst, const void* src, uint32_t bytes) {
    asm volatile("cp.async.cg.shared.global [%0], [%1], 16, %2;" :: "r"(dst), "l"(src), "r"(bytes));
}

// ---------------- precompute: bf16 hi/lo split tables ----------------
__global__ void cvt_kernel(const float* __restrict__ w5, const float* __restrict__ emb) {
    const int i = blockIdx.x * 256 + threadIdx.x;
    if (i < T * D) {
        float x = w5[i];
        __nv_bfloat16 h = __float2bfloat16(x);
        g_w5_hi[i] = h;
        g_w5_lo[i] = __float2bfloat16(x - __bfloat162float(h));
    }
    if (i < (T + 1) * D) {
        float x = emb[i];
        __nv_bfloat16 h = __float2bfloat16(x);
        g_emb_hi[i] = h;
        g_emb_lo[i] = __float2bfloat16(x - __bfloat162float(h));
    }
}

// ---------------- dm + zero norms ----------------
__global__ void dm_kernel(const float* __restrict__ data) {
    const int b = blockIdx.x;
    const int d = threadIdx.x;
    if (b == 0 && d < 5 * B) g_norm2[d] = 0.f;
    const float* p = data + (size_t)b * L * D + d;
    float s = 0.f;
#pragma unroll 8
    for (int l = 0; l < L; ++l) s += p[(size_t)l * D];
    g_dm[b * D + d] = s * (1.0f / (float)L);
}

// ---------------- q[w][b,t] = dm[b,:] . W_w[t,:] ----------------
__global__ void q_kernel(const float* __restrict__ W1, const float* __restrict__ W2,
                         const float* __restrict__ W3, const float* __restrict__ W4) {
    __shared__ float dmt[D][B];
    const int tid = threadIdx.x;
    for (int i = tid; i < B * D; i += 256) {
        int b = i >> 8;
        int d = i & 255;
        dmt[d][b] = g_dm[i];
    }
    __syncthreads();

    const float* W = (blockIdx.y == 0) ? W1 : (blockIdx.y == 1) ? W2
                   : (blockIdx.y == 2) ? W3 : W4;
    float* q = g_q + (size_t)blockIdx.y * B * T;

    const int warp = tid >> 5;
    const int lane = tid & 31;
    const int t0 = blockIdx.x * 128 + warp * 16;

    for (int it = 0; it < 16; ++it) {
        const int t = t0 + it;
        if (t >= T) break;
        const float4* wr = (const float4*)(W + (size_t)t * D);
        float s = 0.f;
#pragma unroll
        for (int k4 = 0; k4 < D / 4; ++k4) {
            float4 w4 = __ldg(&wr[k4]);
            const int d = k4 * 4;
            s += w4.x * dmt[d + 0][lane];
            s += w4.y * dmt[d + 1][lane];
            s += w4.z * dmt[d + 2][lane];
            s += w4.w * dmt[d + 3][lane];
        }
        q[(size_t)lane * T + t] = s;
    }
}

// ---------------- main fused HMMA kernel (v2: cp.async, 2 CTAs/SM) ----------------
// CTA tile: M=L=128, N=TN=64, K=256 in 8 chunks of 32. Split bf16: hh + hl + lh.
// SMEM (dynamic, bytes):
#define SM_EID  0
#define SM_RED  512
#define SM_AH   1536                  // 2 stages x 10240
#define SM_AL   (SM_AH + 2 * 10240)
#define SM_BH   (SM_AL + 2 * 10240)   // 2 stages x 5120
#define SM_BL   (SM_BH + 2 * 5120)
#define SM_BYTES (SM_BL + 2 * 5120)

__global__ __launch_bounds__(256, 2)
void item_kernel(const int* __restrict__ event_type,
                 const float* __restrict__ corr,
                 const float* __restrict__ drop) {
    extern __shared__ char smem[];
    const uint32_t sb = smem_u32(smem);
    int* sEid = (int*)(smem + SM_EID);
    float (*red)[TN] = (float (*)[TN])(smem + SM_RED);

    const int tid  = threadIdx.x;
    const int warp = tid >> 5;
    const int lane = tid & 31;
    const int wm   = warp & 3;        // M block (32 rows)
    const int wn   = warp >> 2;       // N block (32 cols)
    const int b     = blockIdx.y;
    const int tBase = blockIdx.x * TN;

    if (tid < L) sEid[tid] = event_type[b * L + tid];
    __syncthreads();

    // ---- load mapping ----
    // A: 128 rows x 64B x 2 arrays per chunk; row = tid>>1, quarters q = (tid&1)*2 + {0,1}
    const int arow = tid >> 1;
    const int aq0  = (tid & 1) * 2;
    const int eidA = sEid[arow];
    const char* gAh = (const char*)(g_emb_hi + (size_t)eidA * D);
    const char* gAl = (const char*)(g_emb_lo + (size_t)eidA * D);
    // B: 64 rows x 64B x 2 arrays; brow = tid>>2, quarter bq = tid&3
    const int brow = tid >> 2;
    const int bq   = tid & 3;
    const int trow = tBase + brow;
    const bool tOk = trow < T;
    const char* gBh = (const char*)(g_w5_hi + (size_t)(tOk ? trow : 0) * D);
    const char* gBl = (const char*)(g_w5_lo + (size_t)(tOk ? trow : 0) * D);
    const uint32_t bbytes = tOk ? 16u : 0u;

    const uint32_t dAh = sb + SM_AH + arow * 80;
    const uint32_t dAl = sb + SM_AL + arow * 80;
    const uint32_t dBh = sb + SM_BH + brow * 80;
    const uint32_t dBl = sb + SM_BL + brow * 80;

    auto issue = [&](int c, int st) {
        const int go = c * 64;
        const uint32_t so = st ? 10240u : 0u;
        const uint32_t sob = st ? 5120u : 0u;
        cp16(dAh + so + (aq0 + 0) * 16, gAh + go + (aq0 + 0) * 16);
        cp16(dAh + so + (aq0 + 1) * 16, gAh + go + (aq0 + 1) * 16);
        cp16(dAl + so + (aq0 + 0) * 16, gAl + go + (aq0 + 0) * 16);
        cp16(dAl + so + (aq0 + 1) * 16, gAl + go + (aq0 + 1) * 16);
        cp16z(dBh + sob + bq * 16, gBh + go + bq * 16, bbytes);
        cp16z(dBl + sob + bq * 16, gBl + go + bq * 16, bbytes);
        asm volatile("cp.async.commit_group;" ::: "memory");
    };

    float acc[2][4][4];
#pragma unroll
    for (int i = 0; i < 2; ++i)
#pragma unroll
        for (int j = 0; j < 4; ++j)
#pragma unroll
            for (int r = 0; r < 4; ++r) acc[i][j][r] = 0.f;

    // ldmatrix fragment addresses
    const int arow_base = wm * 32 + ((lane >> 3) & 1) * 8 + (lane & 7);
    const int acol_sub  = (lane >> 4) * 8;
    const int brow_base = wn * 32 + ((lane >> 4) & 1) * 8 + (lane & 7);
    const int bcol_sub  = ((lane >> 3) & 1) * 8;

    issue(0, 0);

#pragma unroll 1
    for (int c = 0; c < 8; ++c) {
        const int st = c & 1;
        if (c < 7) {
            issue(c + 1, st ^ 1);
            asm volatile("cp.async.wait_group 1;" ::: "memory");
        } else {
            asm volatile("cp.async.wait_group 0;" ::: "memory");
        }
        __syncthreads();

        const uint32_t aAh = sb + SM_AH + (st ? 10240u : 0u);
        const uint32_t aAl = sb + SM_AL + (st ? 10240u : 0u);
        const uint32_t aBh = sb + SM_BH + (st ? 5120u : 0u);
        const uint32_t aBl = sb + SM_BL + (st ? 5120u : 0u);

#pragma unroll
        for (int kk = 0; kk < 2; ++kk) {
            uint32_t a_h[2][4], a_l[2][4], b_h[4][2], b_l[4][2];
#pragma unroll
            for (int i = 0; i < 2; ++i) {
                const uint32_t off = (uint32_t)((arow_base + i * 16) * SA + kk * 16 + acol_sub) * 2;
                ldm_x4(a_h[i], aAh + off);
                ldm_x4(a_l[i], aAl + off);
            }
#pragma unroll
            for (int jp = 0; jp < 2; ++jp) {
                const uint32_t off = (uint32_t)((brow_base + jp * 16) * SA + kk * 16 + bcol_sub) * 2;
                ldm_x4(&b_h[jp * 2][0], aBh + off);
                ldm_x4(&b_l[jp * 2][0], aBl + off);
            }
#pragma unroll
            for (int i = 0; i < 2; ++i)
#pragma unroll
                for (int j = 0; j < 4; ++j) {
                    mma16816(acc[i][j], a_h[i], b_h[j]);
                    mma16816(acc[i][j], a_h[i], b_l[j]);
                    mma16816(acc[i][j], a_l[i], b_h[j]);
                }
        }
        __syncthreads();
    }

    // ---- fused epilogue: tanh * drop * corr, reduce over l ----
    float pcol[8];
#pragma unroll
    for (int k = 0; k < 8; ++k) pcol[k] = 0.f;

#pragma unroll
    for (int i = 0; i < 2; ++i) {
#pragma unroll
        for (int p = 0; p < 2; ++p) {
            const int r = wm * 32 + i * 16 + p * 8 + (lane >> 2);   // l index
            const int e = sEid[r];
            const float* dr = drop + ((size_t)(b * L + r)) * T;
            const float* cr = corr + (size_t)(e - 1) * T;
#pragma unroll
            for (int j = 0; j < 4; ++j) {
                const int col = tBase + wn * 32 + j * 8 + (lane & 3) * 2;
                if (e > 0 && col < T) {
                    const float2 d2 = __ldg((const float2*)(dr + col));
                    const float2 c2 = __ldg((const float2*)(cr + col));
                    pcol[j * 2 + 0] += fast_tanh(acc[i][j][p * 2 + 0]) * d2.x * c2.x;
                    pcol[j * 2 + 1] += fast_tanh(acc[i][j][p * 2 + 1]) * d2.y * c2.y;
                }
            }
        }
    }

#pragma unroll
    for (int mask = 4; mask <= 16; mask <<= 1)
#pragma unroll
        for (int k = 0; k < 8; ++k)
            pcol[k] += __shfl_xor_sync(0xffffffffu, pcol[k], mask);

    if (lane < 4) {
#pragma unroll
        for (int j = 0; j < 4; ++j) {
            red[wm][wn * 32 + j * 8 + lane * 2 + 0] = pcol[j * 2 + 0];
            red[wm][wn * 32 + j * 8 + lane * 2 + 1] = pcol[j * 2 + 1];
        }
    }
    __syncthreads();

    if (tid < TN) {
        const int t = tBase + tid;
        if (t < T) {
            const float s = red[0][tid] + red[1][tid] + red[2][tid] + red[3][tid];
            g_item[(size_t)b * T + t] = s;
        }
    }
}

// ---------------- norms ----------------
__global__ void norm_kernel() {
    const int b = blockIdx.x, s = blockIdx.y, tid = threadIdx.x;
    const int t0 = s * (T / NSPLIT), t1 = t0 + (T / NSPLIT);
    float a0 = 0, a1 = 0, a2 = 0, a3 = 0, a4 = 0;
    for (int t = t0 + tid; t < t1; t += 256) {
        float v;
        v = g_q[0 * B * T + (size_t)b * T + t]; a0 += v * v;
        v = g_q[1 * B * T + (size_t)b * T + t]; a1 += v * v;
        v = g_q[2 * B * T + (size_t)b * T + t]; a2 += v * v;
        v = g_q[3 * B * T + (size_t)b * T + t]; a3 += v * v;
        v = g_item[(size_t)b * T + t];          a4 += v * v;
    }
#pragma unroll
    for (int o = 16; o; o >>= 1) {
        a0 += __shfl_xor_sync(0xffffffffu, a0, o);
        a1 += __shfl_xor_sync(0xffffffffu, a1, o);
        a2 += __shfl_xor_sync(0xffffffffu, a2, o);
        a3 += __shfl_xor_sync(0xffffffffu, a3, o);
        a4 += __shfl_xor_sync(0xffffffffu, a4, o);
    }
    __shared__ float sm[5][8];
    if ((tid & 31) == 0) {
        const int w = tid >> 5;
        sm[0][w] = a0; sm[1][w] = a1; sm[2][w] = a2; sm[3][w] = a3; sm[4][w] = a4;
    }
    __syncthreads();
    if (tid < 5) {
        float t5 = 0;
#pragma unroll
        for (int k = 0; k < 8; ++k) t5 += sm[tid][k];
        atomicAdd(&g_norm2[tid * B + b], t5);
    }
}

// ---------------- final combine ----------------
__global__ void final_kernel(const float* __restrict__ pa, const float* __restrict__ pb,
                             const float* __restrict__ pc, const float* __restrict__ pd,
                             float* __restrict__ out) {
    const int b = blockIdx.y;
    const int t = blockIdx.x * 256 + threadIdx.x;
    if (t >= T) return;
    auto inv = [](float n2) { return (n2 > 1e-10f) ? rsqrtf(n2) : 1e5f; };
    const float i0 = inv(g_norm2[0 * B + b]);
    const float i1 = inv(g_norm2[1 * B + b]);
    const float i2 = inv(g_norm2[2 * B + b]);
    const float i3 = inv(g_norm2[3 * B + b]);
    const float i4 = inv(g_norm2[4 * B + b]);
    const float ca = pa[0], cb = pb[0], cc = pc[0], cd = pd[0];
    float s = g_q[0 * B * T + (size_t)b * T + t] * i0 * ca
            + g_q[1 * B * T + (size_t)b * T + t] * i1 * cb
            + g_q[2 * B * T + (size_t)b * T + t] * i2 * cc
            + g_q[3 * B * T + (size_t)b * T + t] * i3 * cd
            + g_item[(size_t)b * T + t] * i4;
    out[(size_t)b * T + t] = tanhf(s);
}

// ---------------- target ----------------
__global__ void target_fill(float* __restrict__ tgt) {
    const int i = blockIdx.x * 256 + threadIdx.x;
    if (i < B * T) tgt[i] = 1.f;
}

__global__ void target_scatter(const int* __restrict__ event_type, float* __restrict__ tgt) {
    const int i = blockIdx.x * 256 + threadIdx.x;
    if (i < B * L) {
        const int e = event_type[i];
        if (e != 0) tgt[(size_t)(i >> 7) * T + (e - 1)] = 0.f;
    }
}

// ---------------- launch ----------------
extern "C" void kernel_launch(void* const* d_in, const int* in_sizes, int n_in,
                              void* d_out, int out_size) {
    const float* data = (const float*)d_in[0];
    const int*   ev   = (const int*)d_in[1];
    const float* emb  = (const float*)d_in[2];
    const float* corr = (const float*)d_in[3];
    const float* W1   = (const float*)d_in[4];
    const float* W2   = (const float*)d_in[5];
    const float* W3   = (const float*)d_in[6];
    const float* W4   = (const float*)d_in[7];
    const float* W5   = (const float*)d_in[8];
    const float* a    = (const float*)d_in[9];
    const float* bb   = (const float*)d_in[10];
    const float* c    = (const float*)d_in[11];
    const float* dd   = (const float*)d_in[12];
    const float* drop = (const float*)d_in[13];

    float* out = (float*)d_out;
    float* tgt = out + B * T;

    cudaFuncSetAttribute(item_kernel, cudaFuncAttributeMaxDynamicSharedMemorySize, SM_BYTES);

    cvt_kernel<<<((T + 1) * D + 255) / 256, 256>>>(W5, emb);
    dm_kernel<<<B, 256>>>(data);
    q_kernel<<<dim3((T + 127) / 128, 4), 256>>>(W1, W2, W3, W4);
    item_kernel<<<dim3(NTILES, B), 256, SM_BYTES>>>(ev, corr, drop);
    norm_kernel<<<dim3(B, NSPLIT), 256>>>();
    final_kernel<<<dim3((T + 255) / 256, B), 256>>>(a, bb, c, dd, out);
    target_fill<<<(B * T + 255) / 256, 256>>>(tgt);
    target_scatter<<<(B * L + 255) / 256, 256>>>(ev, tgt);
}